// round 1
// baseline (speedup 1.0000x reference)
#include <cuda_runtime.h>

// ---------------- problem constants ----------------
#define HH    96
#define WW    96
#define CC    64
#define BB    8
#define NPIX  (HH*WW)        // 9216
#define NPTS  9
#define OC    64

typedef unsigned long long ull;

// ---------------- scratch (no allocations allowed) ----------------
__device__ float g_xt[BB * NPIX * CC];        // x transposed to (b, h, w, c)  18.9 MB
__device__ float g_w2t[NPTS * CC * OC];       // w_ker reorganized to [n][c][oc]
__device__ int4  g_meta[BB * NPTS * NPIX];    // per (b,n,pix): x0,y0, lx,ly (as bits)

// ---------------- f32x2 helpers (FFMA2 only reachable via PTX) ----------------
__device__ __forceinline__ ull pack2(float lo, float hi) {
    ull r; asm("mov.b64 %0, {%1,%2};" : "=l"(r) : "f"(lo), "f"(hi)); return r;
}
__device__ __forceinline__ void unpack2(ull v, float& lo, float& hi) {
    asm("mov.b64 {%0,%1}, %2;" : "=f"(lo), "=f"(hi) : "l"(v));
}
__device__ __forceinline__ void fma2(ull& d, ull a, ull b) {
    asm("fma.rn.f32x2 %0, %1, %2, %0;" : "+l"(d) : "l"(a), "l"(b));
}

// ================= K1: transpose x (b,c,h,w) -> (b,hw,c) =================
__global__ __launch_bounds__(256) void k_transpose(const float* __restrict__ x) {
    __shared__ float tile[64][65];
    int b  = blockIdx.y;
    int p0 = blockIdx.x << 6;           // 64 positions per block
    int t  = threadIdx.x;
    #pragma unroll
    for (int i = t; i < 4096; i += 256) {
        int c = i >> 6, p = i & 63;
        tile[c][p] = x[((size_t)(b * 64 + c)) * NPIX + p0 + p];
    }
    __syncthreads();
    #pragma unroll
    for (int i = t; i < 4096; i += 256) {
        int p = i >> 6, c = i & 63;
        g_xt[((size_t)b * NPIX + p0 + p) * 64 + c] = tile[c][p];
    }
}

// ================= K0: w_ker (oc,c,kr,kc) -> w2t[n][c][oc] =================
__global__ __launch_bounds__(256) void k_wt(const float* __restrict__ wker) {
    int i = blockIdx.x * 256 + threadIdx.x;
    if (i < NPTS * CC * OC) {
        int n = i / (CC * OC);
        int r = i - n * (CC * OC);
        int c = r >> 6, oc = r & 63;
        g_w2t[i] = wker[(oc * 64 + c) * 9 + n];
    }
}

// ================= K2: offset conv + bilinear metadata =================
// tile 16x16 pixels, all 64 channel planes (18x18 halo) + all weights in smem.
// 18 outputs computed as 9 f32x2 accumulators per pixel.
#define SMEM_OFF ((64 * 324 + 10368) * 4)
__global__ __launch_bounds__(256) void k_offsets(const float* __restrict__ x,
                                                 const float* __restrict__ wof,
                                                 const float* __restrict__ bof) {
    extern __shared__ float sm2[];
    float* xs  = sm2;              // [c][18][18]
    float* wsm = sm2 + 64 * 324;   // [c][tap][o=18]

    int b  = blockIdx.z;
    int h0 = blockIdx.y << 4, w0 = blockIdx.x << 4;
    int tx = threadIdx.x, ty = threadIdx.y;
    int tid = (ty << 4) + tx;

    for (int i = tid; i < 10368; i += 256) {
        int c = i / 162, r = i - c * 162;
        int tap = r / 18, o = r - tap * 18;
        wsm[i] = wof[(o * 64 + c) * 9 + tap];
    }
    for (int i = tid; i < 64 * 324; i += 256) {
        int c = i / 324, r = i - c * 324;
        int rr = r / 18, cc2 = r - rr * 18;
        int gh = h0 - 1 + rr, gw = w0 - 1 + cc2;
        float v = 0.f;
        if ((unsigned)gh < 96u && (unsigned)gw < 96u)
            v = x[(((size_t)b * 64 + c) * 96 + gh) * 96 + gw];
        xs[i] = v;
    }

    ull acc[9];
    #pragma unroll
    for (int j = 0; j < 9; j++) acc[j] = pack2(bof[2 * j], bof[2 * j + 1]);
    __syncthreads();

    const float* xp = xs + ty * 18 + tx;
    #pragma unroll 2
    for (int c = 0; c < 64; c++) {
        const float* xc = xp + c * 324;
        const ull*   wc = (const ull*)(wsm + c * 162);
        #pragma unroll
        for (int tap = 0; tap < 9; tap++) {
            float xv = xc[(tap / 3) * 18 + (tap % 3)];
            ull xv2 = pack2(xv, xv);
            #pragma unroll
            for (int j = 0; j < 9; j++) fma2(acc[j], wc[tap * 9 + j], xv2);
        }
    }

    float off[18];
    #pragma unroll
    for (int j = 0; j < 9; j++) unpack2(acc[j], off[2 * j], off[2 * j + 1]);

    int h = h0 + ty, w = w0 + tx;
    int pix = h * 96 + w;
    #pragma unroll
    for (int n = 0; n < 9; n++) {
        float px = (float)(h + n / 3 - 1) + off[n];
        float py = (float)(w + n % 3 - 1) + off[9 + n];
        px = fminf(fmaxf(px, -10000.f), 10000.f);  // keep int conversion safe
        py = fminf(fmaxf(py, -10000.f), 10000.f);
        float fx = floorf(px), fy = floorf(py);
        g_meta[((size_t)b * 9 + n) * NPIX + pix] =
            make_int4((int)fx, (int)fy, __float_as_int(px - fx), __float_as_int(py - fy));
    }
}

// ================= K3: fused bilinear sample + main conv (GEMM) =================
// block = 256 threads, tile = 256 pixels x 64 oc, loop over n:
//   phase A: 4-lane groups gather 64B-contiguous channel slices of each corner,
//            blend, stage A[c][pix] in smem; stage w2t[n] (64x64) in smem.
//   phase B: GEMM; thread = 4 pixels x 16 oc, f32x2 accumulators.
#define AP 260                                   // pixel pitch (bank-friendly)
#define SMEM_MAIN ((64 * AP + 4096) * 4)         // 82944 B -> 2 blocks/SM
__global__ __launch_bounds__(256, 2) void k_main(const float* __restrict__ bker,
                                                 float* __restrict__ out) {
    extern __shared__ float sm[];
    float* As = sm;                // [c=64][AP]
    float* ws = sm + 64 * AP;      // [c=64][oc=64]

    int b  = blockIdx.y;
    int p0 = blockIdx.x << 8;      // 256 pixels per block
    int t  = threadIdx.x;
    int g  = t >> 2, q = t & 3;            // sampling: 4-lane groups per pixel
    int quad = t & 63, ocg = t >> 6;       // gemm: 4-pixel quad, 16-oc group

    const float* xb = g_xt + (size_t)b * (NPIX * CC);

    ull acc[4][8];
    #pragma unroll
    for (int pi = 0; pi < 4; pi++)
        #pragma unroll
        for (int j = 0; j < 8; j++) acc[pi][j] = 0ull;

    for (int n = 0; n < 9; n++) {
        if (n) __syncthreads();

        // stage weights for this n (coalesced float4)
        {
            const float4* src = (const float4*)(g_w2t + n * (CC * OC));
            float4* dst = (float4*)ws;
            #pragma unroll
            for (int i = 0; i < 4; i++) dst[t + i * 256] = src[t + i * 256];
        }

        // ---- phase A: sample 256 pixels x 64 channels into As[c][pix] ----
        #pragma unroll
        for (int it = 0; it < 4; it++) {
            int lp = g + (it << 6);
            int pp = p0 + lp;
            int4 m = g_meta[((size_t)b * 9 + n) * NPIX + pp];
            float lx = __int_as_float(m.z), ly = __int_as_float(m.w);
            float w00 = (1.f - lx) * (1.f - ly);
            float w10 = lx * (1.f - ly);
            float w01 = (1.f - lx) * ly;
            float w11 = lx * ly;
            int x0 = m.x, y0 = m.y, x1 = x0 + 1, y1 = y0 + 1;
            if ((unsigned)x0 >= 96u) { w00 = 0.f; w01 = 0.f; }
            if ((unsigned)x1 >= 96u) { w10 = 0.f; w11 = 0.f; }
            if ((unsigned)y0 >= 96u) { w00 = 0.f; w10 = 0.f; }
            if ((unsigned)y1 >= 96u) { w01 = 0.f; w11 = 0.f; }
            int cx0 = min(max(x0, 0), 95), cx1 = min(max(x1, 0), 95);
            int cy0 = min(max(y0, 0), 95), cy1 = min(max(y1, 0), 95);
            const float* p00 = xb + ((cx0 * 96 + cy0) << 6);
            const float* p10 = xb + ((cx1 * 96 + cy0) << 6);
            const float* p01 = xb + ((cx0 * 96 + cy1) << 6);
            const float* p11 = xb + ((cx1 * 96 + cy1) << 6);
            #pragma unroll
            for (int ch = 0; ch < 4; ch++) {
                int c0 = (ch << 4) + (q << 2);    // 4 lanes cover 64B of a corner row
                float4 v00 = *(const float4*)(p00 + c0);
                float4 v10 = *(const float4*)(p10 + c0);
                float4 v01 = *(const float4*)(p01 + c0);
                float4 v11 = *(const float4*)(p11 + c0);
                float sx = w00 * v00.x + w10 * v10.x + w01 * v01.x + w11 * v11.x;
                float sy = w00 * v00.y + w10 * v10.y + w01 * v01.y + w11 * v11.y;
                float sz = w00 * v00.z + w10 * v10.z + w01 * v01.z + w11 * v11.z;
                float sw = w00 * v00.w + w10 * v10.w + w01 * v01.w + w11 * v11.w;
                As[(c0 + 0) * AP + lp] = sx;
                As[(c0 + 1) * AP + lp] = sy;
                As[(c0 + 2) * AP + lp] = sz;
                As[(c0 + 3) * AP + lp] = sw;
            }
        }
        __syncthreads();

        // ---- phase B: GEMM, thread = 4 pixels x 16 oc ----
        const float* Ap = As + (quad << 2);
        #pragma unroll 4
        for (int c = 0; c < 64; c++) {
            float4 a = *(const float4*)(Ap + c * AP);       // LDS.128, conflict-free
            const ull* wr = (const ull*)(ws + c * 64) + (ocg << 3);  // broadcast
            ull a0 = pack2(a.x, a.x);
            ull a1 = pack2(a.y, a.y);
            ull a2 = pack2(a.z, a.z);
            ull a3 = pack2(a.w, a.w);
            #pragma unroll
            for (int j = 0; j < 8; j++) {
                ull wv = wr[j];
                fma2(acc[0][j], wv, a0);
                fma2(acc[1][j], wv, a1);
                fma2(acc[2][j], wv, a2);
                fma2(acc[3][j], wv, a3);
            }
        }
    }

    // ---- epilogue: add bias, store (b, oc, h, w) ----
    int o0  = ocg << 4;
    int pp0 = p0 + (quad << 2);
    float* ob = out + (size_t)b * OC * NPIX;
    #pragma unroll
    for (int j = 0; j < 8; j++) {
        float b0 = bker[o0 + 2 * j], b1 = bker[o0 + 2 * j + 1];
        float lo[4], hi[4];
        #pragma unroll
        for (int pi = 0; pi < 4; pi++) unpack2(acc[pi][j], lo[pi], hi[pi]);
        float4 vlo = make_float4(lo[0] + b0, lo[1] + b0, lo[2] + b0, lo[3] + b0);
        float4 vhi = make_float4(hi[0] + b1, hi[1] + b1, hi[2] + b1, hi[3] + b1);
        *(float4*)(ob + (size_t)(o0 + 2 * j)     * NPIX + pp0) = vlo;
        *(float4*)(ob + (size_t)(o0 + 2 * j + 1) * NPIX + pp0) = vhi;
    }
}

// ================= launch =================
extern "C" void kernel_launch(void* const* d_in, const int* in_sizes, int n_in,
                              void* d_out, int out_size) {
    const float* x     = (const float*)d_in[0];
    const float* w_off = (const float*)d_in[1];
    const float* b_off = (const float*)d_in[2];
    const float* w_ker = (const float*)d_in[3];
    const float* b_ker = (const float*)d_in[4];
    float* out = (float*)d_out;

    cudaFuncSetAttribute(k_offsets, cudaFuncAttributeMaxDynamicSharedMemorySize, SMEM_OFF);
    cudaFuncSetAttribute(k_main,    cudaFuncAttributeMaxDynamicSharedMemorySize, SMEM_MAIN);

    k_transpose<<<dim3(NPIX / 64, BB), 256>>>(x);
    k_wt<<<(NPTS * CC * OC + 255) / 256, 256>>>(w_ker);
    k_offsets<<<dim3(6, 6, BB), dim3(16, 16), SMEM_OFF>>>(x, w_off, b_off);
    k_main<<<dim3(NPIX / 256, BB), 256, SMEM_MAIN>>>(b_ker, out);
}

// round 3
// speedup vs baseline: 1.0405x; 1.0405x over previous
#include <cuda_runtime.h>
#include <cuda_bf16.h>

// ---------------- constants ----------------
#define HH 96
#define WW 96
#define NPIX 9216
#define BB 8

typedef unsigned int u32;
typedef unsigned long long ull;

// ---------------- scratch ----------------
__device__ float g_xt[BB * NPIX * 64];            // x channels-last (b,h,w,c)
__device__ unsigned short g_wbhi[9 * 64 * 64];    // main-conv B bf16 hi, swizzled [n][oc][ch]
__device__ unsigned short g_wblo[9 * 64 * 64];    // lo
__device__ unsigned short g_wobhi[9 * 32 * 64];   // offset-conv B bf16 hi (24 used rows, pad 32)
__device__ unsigned short g_woblo[9 * 32 * 64];

// ---------------- helpers ----------------
__device__ __forceinline__ u32 s2u(const void* p) {
    u32 a; asm("{ .reg .u64 t; cvta.to.shared.u64 t, %1; cvt.u32.u64 %0, t; }" : "=r"(a) : "l"(p));
    return a;
}
__device__ __forceinline__ u32 swz(u32 b) { return b ^ ((b >> 3) & 0x70); }

__device__ __forceinline__ void ldsm4(u32 a, u32& r0, u32& r1, u32& r2, u32& r3) {
    asm volatile("ldmatrix.sync.aligned.m8n8.x4.shared.b16 {%0,%1,%2,%3}, [%4];"
                 : "=r"(r0), "=r"(r1), "=r"(r2), "=r"(r3) : "r"(a));
}
__device__ __forceinline__ void mma_bf16(float& d0, float& d1, float& d2, float& d3,
                                         u32 a0, u32 a1, u32 a2, u32 a3, u32 b0, u32 b1) {
    asm volatile("mma.sync.aligned.m16n8k16.row.col.f32.bf16.bf16.f32 "
                 "{%0,%1,%2,%3},{%4,%5,%6,%7},{%8,%9},{%0,%1,%2,%3};"
                 : "+f"(d0), "+f"(d1), "+f"(d2), "+f"(d3)
                 : "r"(a0), "r"(a1), "r"(a2), "r"(a3), "r"(b0), "r"(b1));
}
__device__ __forceinline__ void sts64(u32 a, u32 x, u32 y) {
    asm volatile("st.shared.v2.b32 [%0],{%1,%2};" :: "r"(a), "r"(x), "r"(y) : "memory");
}
__device__ __forceinline__ void sts128(u32 a, u32 x, u32 y, u32 z, u32 w) {
    asm volatile("st.shared.v4.b32 [%0],{%1,%2,%3,%4};" :: "r"(a), "r"(x), "r"(y), "r"(z), "r"(w) : "memory");
}
__device__ __forceinline__ u32 bfhi2(float a, float b) {   // truncated bf16 hi parts, packed
    return __byte_perm(__float_as_uint(a), __float_as_uint(b), 0x7632);
}
__device__ __forceinline__ u32 bflo2(float a, float b) {   // residual lo parts, packed
    float la = a - __uint_as_float(__float_as_uint(a) & 0xFFFF0000u);
    float lb = b - __uint_as_float(__float_as_uint(b) & 0xFFFF0000u);
    u32 r; asm("cvt.rn.bf16x2.f32 %0, %1, %2;" : "=r"(r) : "f"(lb), "f"(la));
    return r;
}

// ================= K1: transpose x (b,c,h,w) -> (b,hw,c) =================
__global__ __launch_bounds__(256) void k_transpose(const float* __restrict__ x) {
    __shared__ float tile[64][65];
    int b  = blockIdx.y;
    int p0 = blockIdx.x << 6;
    int t  = threadIdx.x;
    #pragma unroll
    for (int i = t; i < 4096; i += 256) {
        int c = i >> 6, p = i & 63;
        tile[c][p] = x[((size_t)(b * 64 + c)) * NPIX + p0 + p];
    }
    __syncthreads();
    #pragma unroll
    for (int i = t; i < 4096; i += 256) {
        int p = i >> 6, c = i & 63;
        g_xt[((size_t)b * NPIX + p0 + p) * 64 + c] = tile[c][p];
    }
}

// ================= K0: weight prep (bf16 hi/lo, pre-swizzled) =================
__global__ __launch_bounds__(256) void k_prep(const float* __restrict__ wker,
                                              const float* __restrict__ wof) {
    int i = blockIdx.x * 256 + threadIdx.x;
    if (i < 9 * 4096) {
        int n = i >> 12, r = i & 4095, oc = r >> 6, ch = r & 63;
        float v = wker[(oc * 64 + ch) * 9 + n];
        u32 hib = __float_as_uint(v) & 0xFFFF0000u;
        float lv = v - __uint_as_float(hib);
        __nv_bfloat16 lb = __float2bfloat16(lv);
        u32 sw = swz((u32)(oc * 128 + ch * 2)) >> 1;
        g_wbhi[n * 4096 + sw] = (unsigned short)(hib >> 16);
        g_wblo[n * 4096 + sw] = *(unsigned short*)&lb;
    } else {
        int j = i - 9 * 4096;
        if (j < 9 * 2048) {
            int n = j >> 11, r = j & 2047, oc = r >> 6, ch = r & 63;
            float v = (oc < 18) ? wof[(oc * 64 + ch) * 9 + n] : 0.f;
            u32 hib = __float_as_uint(v) & 0xFFFF0000u;
            float lv = v - __uint_as_float(hib);
            __nv_bfloat16 lb = __float2bfloat16(lv);
            u32 sw = swz((u32)(oc * 128 + ch * 2)) >> 1;
            g_wobhi[n * 2048 + sw] = (unsigned short)(hib >> 16);
            g_woblo[n * 2048 + sw] = *(unsigned short*)&lb;
        }
    }
}

// ================= K_MAIN: offset conv + bilinear + main conv, all HMMA =================
// block = 256 threads (8 warps), tile = 128 pixels (M=128), oc = 64 (N=64)
#define A_HI    0
#define A_LO    16384
#define B_HI    32768
#define B_LO    40960
#define OFF_MO  49152
#define OFF_MW  67584
#define SMEM_MAIN 86016

__global__ __launch_bounds__(256, 2) void k_main(const float* __restrict__ bof,
                                                 const float* __restrict__ bker,
                                                 float* __restrict__ out) {
    extern __shared__ char smc[];
    u32 sb = s2u(smc);
    int t = threadIdx.x, wid = t >> 5, ln = t & 31;
    int b = blockIdx.y;
    int p0 = blockIdx.x * 128;
    const float* xb = g_xt + (size_t)b * NPIX * 64;
    u32 aHiB = sb + A_HI, aLoB = sb + A_LO, bHiB = sb + B_HI, bLoB = sb + B_LO;

    // ================= PHASE 0: offset conv (K=576 over 9 taps, N=24 padded) =================
    float acc0[3][4];
    #pragma unroll
    for (int nt = 0; nt < 3; nt++)
        #pragma unroll
        for (int j = 0; j < 4; j++) acc0[nt][j] = 0.f;

    {
        int lp = t >> 1, q = t & 1;
        int pix = p0 + lp, hh = pix / 96, ww = pix - hh * 96;

        for (int tap = 0; tap < 9; tap++) {
            __syncthreads();
            // stage B for this tap: 4KB hi + 4KB lo
            {
                const uint4* sh = (const uint4*)g_wobhi + tap * 256;
                const uint4* sl = (const uint4*)g_woblo + tap * 256;
                if (t < 256) { ((uint4*)(smc + B_HI))[t] = sh[t]; ((uint4*)(smc + B_LO))[t] = sl[t]; }
            }
            // build A: shifted channels-last copy, f32 -> bf16 hi/lo
            {
                int sh_ = hh + tap / 3 - 1, sw_ = ww + tap % 3 - 1;
                bool ok = ((unsigned)sh_ < 96u) & ((unsigned)sw_ < 96u);
                float4 v[8];
                if (ok) {
                    const float4* src = (const float4*)(xb + ((size_t)(sh_ * 96 + sw_)) * 64 + q * 32);
                    #pragma unroll
                    for (int j = 0; j < 8; j++) v[j] = src[j];
                } else {
                    #pragma unroll
                    for (int j = 0; j < 8; j++) v[j] = make_float4(0.f, 0.f, 0.f, 0.f);
                }
                u32 rowb = (u32)(lp * 128 + q * 64);
                #pragma unroll
                for (int j = 0; j < 4; j++) {
                    u32 sa = swz(rowb + j * 16);
                    sts128(aHiB + sa, bfhi2(v[2*j].x, v[2*j].y), bfhi2(v[2*j].z, v[2*j].w),
                                      bfhi2(v[2*j+1].x, v[2*j+1].y), bfhi2(v[2*j+1].z, v[2*j+1].w));
                    sts128(aLoB + sa, bflo2(v[2*j].x, v[2*j].y), bflo2(v[2*j].z, v[2*j].w),
                                      bflo2(v[2*j+1].x, v[2*j+1].y), bflo2(v[2*j+1].z, v[2*j+1].w));
                }
            }
            __syncthreads();
            // mma: warp = pixels [wid*16, wid*16+16), ntiles 0..2
            {
                u32 arow = (u32)((wid * 16 + (ln & 15)) * 128 + ((ln >> 4) * 16));
                u32 brow = (u32)(((((ln >> 4) << 3) + (ln & 7))) * 128 + (((ln >> 3) & 1) * 16));
                #pragma unroll
                for (int k = 0; k < 4; k++) {
                    u32 ka = (u32)(k * 32);
                    u32 ah[4], al[4], bh[8], bl[8];
                    ldsm4(aHiB + swz(arow + ka), ah[0], ah[1], ah[2], ah[3]);
                    ldsm4(aLoB + swz(arow + ka), al[0], al[1], al[2], al[3]);
                    ldsm4(bHiB + swz(brow + ka), bh[0], bh[1], bh[2], bh[3]);
                    ldsm4(bHiB + swz(brow + 2048 + ka), bh[4], bh[5], bh[6], bh[7]);
                    ldsm4(bLoB + swz(brow + ka), bl[0], bl[1], bl[2], bl[3]);
                    ldsm4(bLoB + swz(brow + 2048 + ka), bl[4], bl[5], bl[6], bl[7]);
                    #pragma unroll
                    for (int nt = 0; nt < 3; nt++) {
                        mma_bf16(acc0[nt][0], acc0[nt][1], acc0[nt][2], acc0[nt][3],
                                 ah[0], ah[1], ah[2], ah[3], bh[nt*2], bh[nt*2+1]);
                        mma_bf16(acc0[nt][0], acc0[nt][1], acc0[nt][2], acc0[nt][3],
                                 al[0], al[1], al[2], al[3], bh[nt*2], bh[nt*2+1]);
                        mma_bf16(acc0[nt][0], acc0[nt][1], acc0[nt][2], acc0[nt][3],
                                 ah[0], ah[1], ah[2], ah[3], bl[nt*2], bl[nt*2+1]);
                    }
                }
            }
        }
    }
    __syncthreads();
    // stage offset-conv outputs to smem [pix][24] (reuses A region)
    {
        float* dst = (float*)(smc + A_HI);
        int pr = wid * 16 + (ln >> 2);
        int pc = (ln & 3) * 2;
        #pragma unroll
        for (int nt = 0; nt < 3; nt++) {
            dst[pr * 24 + nt * 8 + pc]           = acc0[nt][0];
            dst[pr * 24 + nt * 8 + pc + 1]       = acc0[nt][1];
            dst[(pr + 8) * 24 + nt * 8 + pc]     = acc0[nt][2];
            dst[(pr + 8) * 24 + nt * 8 + pc + 1] = acc0[nt][3];
        }
    }
    __syncthreads();
    // compute bilinear metadata: 128 pix x 9 points
    {
        const float* dsm = (const float*)(smc + A_HI);
        int4*   mo = (int4*)(smc + OFF_MO);
        float4* mw = (float4*)(smc + OFF_MW);
        for (int i = t; i < 1152; i += 256) {
            int lp = i / 9, n = i - lp * 9;
            int pix = p0 + lp, hh = pix / 96, ww = pix - hh * 96;
            float ox = dsm[lp * 24 + n]     + bof[n];
            float oy = dsm[lp * 24 + 9 + n] + bof[9 + n];
            float px = (float)(hh + n / 3 - 1) + ox;
            float py = (float)(ww + n % 3 - 1) + oy;
            px = fminf(fmaxf(px, -10000.f), 10000.f);
            py = fminf(fmaxf(py, -10000.f), 10000.f);
            float fx = floorf(px), fy = floorf(py);
            float lx = px - fx, ly = py - fy;
            int x0 = (int)fx, y0 = (int)fy, x1 = x0 + 1, y1 = y0 + 1;
            float w00 = (1.f - lx) * (1.f - ly);
            float w10 = lx * (1.f - ly);
            float w01 = (1.f - lx) * ly;
            float w11 = lx * ly;
            if ((unsigned)x0 >= 96u) { w00 = 0.f; w01 = 0.f; }
            if ((unsigned)x1 >= 96u) { w10 = 0.f; w11 = 0.f; }
            if ((unsigned)y0 >= 96u) { w00 = 0.f; w10 = 0.f; }
            if ((unsigned)y1 >= 96u) { w01 = 0.f; w11 = 0.f; }
            int cx0 = min(max(x0, 0), 95), cx1 = min(max(x1, 0), 95);
            int cy0 = min(max(y0, 0), 95), cy1 = min(max(y1, 0), 95);
            mo[i] = make_int4((cx0 * 96 + cy0) * 64, (cx1 * 96 + cy0) * 64,
                              (cx0 * 96 + cy1) * 64, (cx1 * 96 + cy1) * 64);
            mw[i] = make_float4(w00, w10, w01, w11);
        }
    }

    // ================= PHASE 1: sampled main conv (K=576 over 9 points) =================
    float acc[2][4][4];
    #pragma unroll
    for (int mt = 0; mt < 2; mt++)
        #pragma unroll
        for (int nt = 0; nt < 4; nt++)
            #pragma unroll
            for (int j = 0; j < 4; j++) acc[mt][nt][j] = 0.f;

    int g2 = ln >> 3, l8 = ln & 7;
    const int4*   mo = (const int4*)(smc + OFF_MO);
    const float4* mw = (const float4*)(smc + OFF_MW);

    for (int n = 0; n < 9; n++) {
        __syncthreads();
        // stage B: 8KB hi + 8KB lo
        {
            const uint4* sh = (const uint4*)g_wbhi + n * 512;
            const uint4* sl = (const uint4*)g_wblo + n * 512;
            uint4* dh = (uint4*)(smc + B_HI);
            uint4* dl = (uint4*)(smc + B_LO);
            dh[t] = sh[t]; dh[t + 256] = sh[t + 256];
            dl[t] = sl[t]; dl[t + 256] = sl[t + 256];
        }
        // sample: warp = pixel, 8-lane groups load full 128B corner lines, shfl-reduce
        #pragma unroll 2
        for (int i = 0; i < 16; i++) {
            int lp = wid * 16 + i;
            int mi = lp * 9 + n;
            int4   o4 = mo[mi];
            float4 w4 = mw[mi];
            int   off = (g2 & 1) ? ((g2 & 2) ? o4.w : o4.y) : ((g2 & 2) ? o4.z : o4.x);
            float wt  = (g2 & 1) ? ((g2 & 2) ? w4.w : w4.y) : ((g2 & 2) ? w4.z : w4.x);
            const float4* src = (const float4*)(xb + off);
            float4 v0 = src[l8];       // ch [l8*4, +4)
            float4 v1 = src[8 + l8];   // ch [32+l8*4, +4)
            float s0x = v0.x * wt, s0y = v0.y * wt, s0z = v0.z * wt, s0w = v0.w * wt;
            float s1x = v1.x * wt, s1y = v1.y * wt, s1z = v1.z * wt, s1w = v1.w * wt;
            s0x += __shfl_xor_sync(0xffffffffu, s0x, 8);
            s0y += __shfl_xor_sync(0xffffffffu, s0y, 8);
            s0z += __shfl_xor_sync(0xffffffffu, s0z, 8);
            s0w += __shfl_xor_sync(0xffffffffu, s0w, 8);
            s1x += __shfl_xor_sync(0xffffffffu, s1x, 8);
            s1y += __shfl_xor_sync(0xffffffffu, s1y, 8);
            s1z += __shfl_xor_sync(0xffffffffu, s1z, 8);
            s1w += __shfl_xor_sync(0xffffffffu, s1w, 8);
            s0x += __shfl_xor_sync(0xffffffffu, s0x, 16);
            s0y += __shfl_xor_sync(0xffffffffu, s0y, 16);
            s0z += __shfl_xor_sync(0xffffffffu, s0z, 16);
            s0w += __shfl_xor_sync(0xffffffffu, s0w, 16);
            s1x += __shfl_xor_sync(0xffffffffu, s1x, 16);
            s1y += __shfl_xor_sync(0xffffffffu, s1y, 16);
            s1z += __shfl_xor_sync(0xffffffffu, s1z, 16);
            s1w += __shfl_xor_sync(0xffffffffu, s1w, 16);
            // g2: 0 -> hi slab0, 1 -> hi slab1, 2 -> lo slab0, 3 -> lo slab1
            int slab = g2 & 1;
            float a0 = slab ? s1x : s0x, a1 = slab ? s1y : s0y;
            float a2 = slab ? s1z : s0z, a3 = slab ? s1w : s0w;
            u32 addr = ((g2 < 2) ? aHiB : aLoB) + swz((u32)(lp * 128 + slab * 64 + l8 * 8));
            if (g2 < 2) sts64(addr, bfhi2(a0, a1), bfhi2(a2, a3));
            else        sts64(addr, bflo2(a0, a1), bflo2(a2, a3));
        }
        __syncthreads();
        // mma: warp (wid&3) = 32-pixel group, (wid>>2) = 32-oc half
        {
            int mbase = (wid & 3) * 32, nbase = (wid >> 2) * 32;
            u32 arow = (u32)((mbase + (ln & 15)) * 128 + ((ln >> 4) * 16));
            u32 brow = (u32)((nbase + ((ln >> 4) << 3) + (ln & 7)) * 128 + (((ln >> 3) & 1) * 16));
            #pragma unroll
            for (int k = 0; k < 4; k++) {
                u32 ka = (u32)(k * 32);
                u32 ah[8], al[8], bh[8], bl[8];
                ldsm4(aHiB + swz(arow + ka),        ah[0], ah[1], ah[2], ah[3]);
                ldsm4(aHiB + swz(arow + 2048 + ka), ah[4], ah[5], ah[6], ah[7]);
                ldsm4(aLoB + swz(arow + ka),        al[0], al[1], al[2], al[3]);
                ldsm4(aLoB + swz(arow + 2048 + ka), al[4], al[5], al[6], al[7]);
                ldsm4(bHiB + swz(brow + ka),        bh[0], bh[1], bh[2], bh[3]);
                ldsm4(bHiB + swz(brow + 2048 + ka), bh[4], bh[5], bh[6], bh[7]);
                ldsm4(bLoB + swz(brow + ka),        bl[0], bl[1], bl[2], bl[3]);
                ldsm4(bLoB + swz(brow + 2048 + ka), bl[4], bl[5], bl[6], bl[7]);
                #pragma unroll
                for (int mt = 0; mt < 2; mt++) {
                    #pragma unroll
                    for (int nt = 0; nt < 4; nt++) {
                        mma_bf16(acc[mt][nt][0], acc[mt][nt][1], acc[mt][nt][2], acc[mt][nt][3],
                                 ah[mt*4], ah[mt*4+1], ah[mt*4+2], ah[mt*4+3], bh[nt*2], bh[nt*2+1]);
                        mma_bf16(acc[mt][nt][0], acc[mt][nt][1], acc[mt][nt][2], acc[mt][nt][3],
                                 al[mt*4], al[mt*4+1], al[mt*4+2], al[mt*4+3], bh[nt*2], bh[nt*2+1]);
                        mma_bf16(acc[mt][nt][0], acc[mt][nt][1], acc[mt][nt][2], acc[mt][nt][3],
                                 ah[mt*4], ah[mt*4+1], ah[mt*4+2], ah[mt*4+3], bl[nt*2], bl[nt*2+1]);
                    }
                }
            }
        }
    }

    // ================= epilogue =================
    {
        int mbase = (wid & 3) * 32, nbase = (wid >> 2) * 32;
        #pragma unroll
        for (int mt = 0; mt < 2; mt++) {
            #pragma unroll
            for (int nt = 0; nt < 4; nt++) {
                int pix = p0 + mbase + mt * 16 + (ln >> 2);
                int oc  = nbase + nt * 8 + (ln & 3) * 2;
                float b0 = __ldg(bker + oc), b1 = __ldg(bker + oc + 1);
                size_t base = ((size_t)(b * 64 + oc)) * NPIX + pix;
                out[base]            = acc[mt][nt][0] + b0;
                out[base + NPIX]     = acc[mt][nt][1] + b1;
                out[base + 8]        = acc[mt][nt][2] + b0;
                out[base + NPIX + 8] = acc[mt][nt][3] + b1;
            }
        }
    }
}

// ================= launch =================
extern "C" void kernel_launch(void* const* d_in, const int* in_sizes, int n_in,
                              void* d_out, int out_size) {
    const float* x     = (const float*)d_in[0];
    const float* w_off = (const float*)d_in[1];
    const float* b_off = (const float*)d_in[2];
    const float* w_ker = (const float*)d_in[3];
    const float* b_ker = (const float*)d_in[4];
    float* out = (float*)d_out;

    cudaFuncSetAttribute(k_main, cudaFuncAttributeMaxDynamicSharedMemorySize, SMEM_MAIN);

    k_transpose<<<dim3(NPIX / 64, BB), 256>>>(x);
    k_prep<<<(9 * 4096 + 9 * 2048 + 255) / 256, 256>>>(w_ker, w_off);
    k_main<<<dim3(NPIX / 128, BB), 256, SMEM_MAIN>>>(b_off, b_ker, out);
}

// round 5
// speedup vs baseline: 1.5351x; 1.4753x over previous
#include <cuda_runtime.h>
#include <cuda_bf16.h>

// ---------------- constants ----------------
#define HH 96
#define WW 96
#define NPIX 9216
#define BB 8

typedef unsigned int u32;
typedef unsigned long long ull;

// ---------------- scratch ----------------
__device__ float g_xt[BB * NPIX * 64];            // x channels-last f32
__device__ u32   g_xbh[BB * NPIX * 32];           // x channels-last bf16 hi (packed pairs)
__device__ u32   g_xbl[BB * NPIX * 32];           // bf16 lo residual
__device__ unsigned short g_wbhi[9 * 64 * 64];    // main-conv B bf16 hi, swizzled [n][oc][ch]
__device__ unsigned short g_wblo[9 * 64 * 64];
__device__ unsigned short g_wobhi[9 * 32 * 64];   // offset-conv B (24 rows used, padded 32)
__device__ unsigned short g_woblo[9 * 32 * 64];

// ---------------- helpers ----------------
__device__ __forceinline__ u32 s2u(const void* p) {
    u32 a; asm("{ .reg .u64 t; cvta.to.shared.u64 t, %1; cvt.u32.u64 %0, t; }" : "=r"(a) : "l"(p));
    return a;
}
__device__ __forceinline__ u32 swz(u32 b) { return b ^ ((b >> 3) & 0x70); }

__device__ __forceinline__ void ldsm4(u32 a, u32& r0, u32& r1, u32& r2, u32& r3) {
    asm volatile("ldmatrix.sync.aligned.m8n8.x4.shared.b16 {%0,%1,%2,%3}, [%4];"
                 : "=r"(r0), "=r"(r1), "=r"(r2), "=r"(r3) : "r"(a));
}
__device__ __forceinline__ void mma_bf16(float& d0, float& d1, float& d2, float& d3,
                                         u32 a0, u32 a1, u32 a2, u32 a3, u32 b0, u32 b1) {
    asm volatile("mma.sync.aligned.m16n8k16.row.col.f32.bf16.bf16.f32 "
                 "{%0,%1,%2,%3},{%4,%5,%6,%7},{%8,%9},{%0,%1,%2,%3};"
                 : "+f"(d0), "+f"(d1), "+f"(d2), "+f"(d3)
                 : "r"(a0), "r"(a1), "r"(a2), "r"(a3), "r"(b0), "r"(b1));
}
__device__ __forceinline__ void sts128(u32 a, u32 x, u32 y, u32 z, u32 w) {
    asm volatile("st.shared.v4.b32 [%0],{%1,%2,%3,%4};" :: "r"(a), "r"(x), "r"(y), "r"(z), "r"(w) : "memory");
}
__device__ __forceinline__ u32 bfhi2(float a, float b) {
    return __byte_perm(__float_as_uint(a), __float_as_uint(b), 0x7632);
}
__device__ __forceinline__ u32 bflo2(float a, float b) {
    float la = a - __uint_as_float(__float_as_uint(a) & 0xFFFF0000u);
    float lb = b - __uint_as_float(__float_as_uint(b) & 0xFFFF0000u);
    u32 r; asm("cvt.rn.bf16x2.f32 %0, %1, %2;" : "=r"(r) : "f"(lb), "f"(la));
    return r;
}
__device__ __forceinline__ ull pack2(float lo, float hi) {
    ull r; asm("mov.b64 %0, {%1,%2};" : "=l"(r) : "f"(lo), "f"(hi)); return r;
}
__device__ __forceinline__ void unpack2(ull v, float& lo, float& hi) {
    asm("mov.b64 {%0,%1}, %2;" : "=f"(lo), "=f"(hi) : "l"(v));
}
__device__ __forceinline__ ull mul2(ull a, ull b) {
    ull r; asm("mul.rn.f32x2 %0, %1, %2;" : "=l"(r) : "l"(a), "l"(b)); return r;
}
__device__ __forceinline__ void fma2(ull& d, ull a, ull b) {
    asm("fma.rn.f32x2 %0, %1, %2, %0;" : "+l"(d) : "l"(a), "l"(b));
}

// ================= K1: transpose + bf16 image emit =================
__global__ __launch_bounds__(256) void k_transpose(const float* __restrict__ x) {
    __shared__ float tile[64][65];
    int b  = blockIdx.y;
    int p0 = blockIdx.x << 6;
    int t  = threadIdx.x;
    #pragma unroll
    for (int i = t; i < 4096; i += 256) {
        int c = i >> 6, p = i & 63;
        tile[c][p] = x[((size_t)(b * 64 + c)) * NPIX + p0 + p];
    }
    __syncthreads();
    #pragma unroll
    for (int i = t; i < 4096; i += 256) {
        int p = i >> 6, c = i & 63;
        g_xt[((size_t)b * NPIX + p0 + p) * 64 + c] = tile[c][p];
    }
    #pragma unroll
    for (int i = t; i < 2048; i += 256) {
        int p = i >> 5, cp = i & 31;
        float v0 = tile[cp * 2][p], v1 = tile[cp * 2 + 1][p];
        size_t idx = ((size_t)b * NPIX + p0 + p) * 32 + cp;
        g_xbh[idx] = bfhi2(v0, v1);
        g_xbl[idx] = bflo2(v0, v1);
    }
}

// ================= K0: weight prep =================
__global__ __launch_bounds__(256) void k_prep(const float* __restrict__ wker,
                                              const float* __restrict__ wof) {
    int i = blockIdx.x * 256 + threadIdx.x;
    if (i < 9 * 4096) {
        int n = i >> 12, r = i & 4095, oc = r >> 6, ch = r & 63;
        float v = wker[(oc * 64 + ch) * 9 + n];
        u32 hib = __float_as_uint(v) & 0xFFFF0000u;
        float lv = v - __uint_as_float(hib);
        __nv_bfloat16 lb = __float2bfloat16(lv);
        u32 sw = swz((u32)(oc * 128 + ch * 2)) >> 1;
        g_wbhi[n * 4096 + sw] = (unsigned short)(hib >> 16);
        g_wblo[n * 4096 + sw] = *(unsigned short*)&lb;
    } else {
        int j = i - 9 * 4096;
        if (j < 9 * 2048) {
            int n = j >> 11, r = j & 2047, oc = r >> 6, ch = r & 63;
            float v = (oc < 18) ? wof[(oc * 64 + ch) * 9 + n] : 0.f;
            u32 hib = __float_as_uint(v) & 0xFFFF0000u;
            float lv = v - __uint_as_float(hib);
            __nv_bfloat16 lb = __float2bfloat16(lv);
            u32 sw = swz((u32)(oc * 128 + ch * 2)) >> 1;
            g_wobhi[n * 2048 + sw] = (unsigned short)(hib >> 16);
            g_woblo[n * 2048 + sw] = *(unsigned short*)&lb;
        }
    }
}

// ================= K_MAIN =================
#define A_HI    0
#define A_LO    16384
#define B_HI    32768
#define B_LO    40960
#define OFF_MO  49152
#define OFF_MW  67584
#define SMEM_MAIN 86016

__global__ __launch_bounds__(256, 2) void k_main(const float* __restrict__ bof,
                                                 const float* __restrict__ bker,
                                                 float* __restrict__ out) {
    extern __shared__ char smc[];
    u32 sb = s2u(smc);
    int t = threadIdx.x, wid = t >> 5, ln = t & 31;
    int b = blockIdx.y;
    int p0 = blockIdx.x * 128;
    const float* xb = g_xt + (size_t)b * NPIX * 64;
    u32 aHiB = sb + A_HI, aLoB = sb + A_LO, bHiB = sb + B_HI, bLoB = sb + B_LO;

    // ================= PHASE 0: offset conv (3-term bf16, N=24 pad 32) =================
    float acc0[3][4];
    #pragma unroll
    for (int nt = 0; nt < 3; nt++)
        #pragma unroll
        for (int j = 0; j < 4; j++) acc0[nt][j] = 0.f;

    {
        int lp = t >> 1, q = t & 1;
        int pix = p0 + lp, hh = pix / 96, ww = pix - hh * 96;
        const u32* xbh = g_xbh + (size_t)b * NPIX * 32;
        const u32* xbl = g_xbl + (size_t)b * NPIX * 32;

        for (int tap = 0; tap < 9; tap++) {
            __syncthreads();
            if (t < 256) {
                ((uint4*)(smc + B_HI))[t] = ((const uint4*)g_wobhi + tap * 256)[t];
                ((uint4*)(smc + B_LO))[t] = ((const uint4*)g_woblo + tap * 256)[t];
            }
            // build A: this thread owns the q-th 64B half of its pixel's 128B row
            {
                int sh_ = hh + tap / 3 - 1, sw_ = ww + tap % 3 - 1;
                bool ok = ((unsigned)sh_ < 96u) & ((unsigned)sw_ < 96u);
                uint4 vh[4], vl[4];
                if (ok) {
                    const uint4* sh4 = (const uint4*)(xbh + (size_t)(sh_ * 96 + sw_) * 32) + q * 4;
                    const uint4* sl4 = (const uint4*)(xbl + (size_t)(sh_ * 96 + sw_) * 32) + q * 4;
                    #pragma unroll
                    for (int j = 0; j < 4; j++) { vh[j] = sh4[j]; vl[j] = sl4[j]; }
                } else {
                    #pragma unroll
                    for (int j = 0; j < 4; j++) vh[j] = vl[j] = make_uint4(0, 0, 0, 0);
                }
                u32 rowb = (u32)(lp * 128 + q * 64);
                #pragma unroll
                for (int j = 0; j < 4; j++) {
                    u32 sa = swz(rowb + j * 16);
                    sts128(aHiB + sa, vh[j].x, vh[j].y, vh[j].z, vh[j].w);
                    sts128(aLoB + sa, vl[j].x, vl[j].y, vl[j].z, vl[j].w);
                }
            }
            __syncthreads();
            {
                u32 arow = (u32)((wid * 16 + (ln & 15)) * 128 + ((ln >> 4) * 16));
                u32 brow = (u32)(((((ln >> 4) << 3) + (ln & 7))) * 128 + (((ln >> 3) & 1) * 16));
                #pragma unroll
                for (int k = 0; k < 4; k++) {
                    u32 ka = (u32)(k * 32);
                    u32 ah[4], al[4], bh[8], bl[8];
                    ldsm4(aHiB + swz(arow + ka), ah[0], ah[1], ah[2], ah[3]);
                    ldsm4(aLoB + swz(arow + ka), al[0], al[1], al[2], al[3]);
                    ldsm4(bHiB + swz(brow + ka), bh[0], bh[1], bh[2], bh[3]);
                    ldsm4(bHiB + swz(brow + 2048 + ka), bh[4], bh[5], bh[6], bh[7]);
                    ldsm4(bLoB + swz(brow + ka), bl[0], bl[1], bl[2], bl[3]);
                    ldsm4(bLoB + swz(brow + 2048 + ka), bl[4], bl[5], bl[6], bl[7]);
                    #pragma unroll
                    for (int nt = 0; nt < 3; nt++) {
                        mma_bf16(acc0[nt][0], acc0[nt][1], acc0[nt][2], acc0[nt][3],
                                 ah[0], ah[1], ah[2], ah[3], bh[nt*2], bh[nt*2+1]);
                        mma_bf16(acc0[nt][0], acc0[nt][1], acc0[nt][2], acc0[nt][3],
                                 al[0], al[1], al[2], al[3], bh[nt*2], bh[nt*2+1]);
                        mma_bf16(acc0[nt][0], acc0[nt][1], acc0[nt][2], acc0[nt][3],
                                 ah[0], ah[1], ah[2], ah[3], bl[nt*2], bl[nt*2+1]);
                    }
                }
            }
        }
    }
    __syncthreads();
    {
        float* dst = (float*)(smc + A_HI);
        int pr = wid * 16 + (ln >> 2);
        int pc = (ln & 3) * 2;
        #pragma unroll
        for (int nt = 0; nt < 3; nt++) {
            dst[pr * 24 + nt * 8 + pc]           = acc0[nt][0];
            dst[pr * 24 + nt * 8 + pc + 1]       = acc0[nt][1];
            dst[(pr + 8) * 24 + nt * 8 + pc]     = acc0[nt][2];
            dst[(pr + 8) * 24 + nt * 8 + pc + 1] = acc0[nt][3];
        }
    }
    __syncthreads();
    {
        const float* dsm = (const float*)(smc + A_HI);
        int4*   mo = (int4*)(smc + OFF_MO);
        float4* mw = (float4*)(smc + OFF_MW);
        for (int i = t; i < 1152; i += 256) {
            int lp = i / 9, n = i - lp * 9;
            int pix = p0 + lp, hh = pix / 96, ww = pix - hh * 96;
            float ox = dsm[lp * 24 + n]     + __ldg(bof + n);
            float oy = dsm[lp * 24 + 9 + n] + __ldg(bof + 9 + n);
            float px = (float)(hh + n / 3 - 1) + ox;
            float py = (float)(ww + n % 3 - 1) + oy;
            px = fminf(fmaxf(px, -10000.f), 10000.f);
            py = fminf(fmaxf(py, -10000.f), 10000.f);
            float fx = floorf(px), fy = floorf(py);
            float lx = px - fx, ly = py - fy;
            int x0 = (int)fx, y0 = (int)fy, x1 = x0 + 1, y1 = y0 + 1;
            float w00 = (1.f - lx) * (1.f - ly);
            float w10 = lx * (1.f - ly);
            float w01 = (1.f - lx) * ly;
            float w11 = lx * ly;
            if ((unsigned)x0 >= 96u) { w00 = 0.f; w01 = 0.f; }
            if ((unsigned)x1 >= 96u) { w10 = 0.f; w11 = 0.f; }
            if ((unsigned)y0 >= 96u) { w00 = 0.f; w10 = 0.f; }
            if ((unsigned)y1 >= 96u) { w01 = 0.f; w11 = 0.f; }
            int cx0 = min(max(x0, 0), 95), cx1 = min(max(x1, 0), 95);
            int cy0 = min(max(y0, 0), 95), cy1 = min(max(y1, 0), 95);
            mo[i] = make_int4((cx0 * 96 + cy0) * 64, (cx1 * 96 + cy0) * 64,
                              (cx0 * 96 + cy1) * 64, (cx1 * 96 + cy1) * 64);
            mw[i] = make_float4(w00, w10, w01, w11);
        }
    }

    // ================= PHASE 1: sampled main conv =================
    float acc[2][4][4];
    #pragma unroll
    for (int mt = 0; mt < 2; mt++)
        #pragma unroll
        for (int nt = 0; nt < 4; nt++)
            #pragma unroll
            for (int j = 0; j < 4; j++) acc[mt][nt][j] = 0.f;

    int l8 = ln & 7, g4 = ln >> 3;     // lane -> (pixel-in-group g4, 8-ch slice l8)
    const int4*   mo = (const int4*)(smc + OFF_MO);
    const float4* mw = (const float4*)(smc + OFF_MW);

    for (int n = 0; n < 9; n++) {
        __syncthreads();
        {
            const uint4* sh = (const uint4*)g_wbhi + n * 512;
            const uint4* sl = (const uint4*)g_wblo + n * 512;
            uint4* dh = (uint4*)(smc + B_HI);
            uint4* dl = (uint4*)(smc + B_LO);
            dh[t] = sh[t]; dh[t + 256] = sh[t + 256];
            dl[t] = sl[t]; dl[t + 256] = sl[t + 256];
        }
        // sample: warp handles 16 pixels in 4 iterations of 4 pixels; lane = 8 channels
        #pragma unroll
        for (int i = 0; i < 4; i++) {
            int lp = wid * 16 + i * 4 + g4;
            int mi = lp * 9 + n;
            int4   o4 = mo[mi];
            float4 w4 = mw[mi];
            const float* pA = xb + o4.x + l8 * 8;
            const float* pB = xb + o4.y + l8 * 8;
            const float* pC = xb + o4.z + l8 * 8;
            const float* pD = xb + o4.w + l8 * 8;
            float4 A0 = *(const float4*)pA, A1 = *(const float4*)(pA + 4);
            float4 B0 = *(const float4*)pB, B1 = *(const float4*)(pB + 4);
            float4 C0 = *(const float4*)pC, C1 = *(const float4*)(pC + 4);
            float4 D0 = *(const float4*)pD, D1 = *(const float4*)(pD + 4);
            ull W00 = pack2(w4.x, w4.x), W10 = pack2(w4.y, w4.y);
            ull W01 = pack2(w4.z, w4.z), W11 = pack2(w4.w, w4.w);
            ull r0 = mul2(pack2(A0.x, A0.y), W00);
            ull r1 = mul2(pack2(A0.z, A0.w), W00);
            ull r2 = mul2(pack2(A1.x, A1.y), W00);
            ull r3 = mul2(pack2(A1.z, A1.w), W00);
            fma2(r0, pack2(B0.x, B0.y), W10); fma2(r1, pack2(B0.z, B0.w), W10);
            fma2(r2, pack2(B1.x, B1.y), W10); fma2(r3, pack2(B1.z, B1.w), W10);
            fma2(r0, pack2(C0.x, C0.y), W01); fma2(r1, pack2(C0.z, C0.w), W01);
            fma2(r2, pack2(C1.x, C1.y), W01); fma2(r3, pack2(C1.z, C1.w), W01);
            fma2(r0, pack2(D0.x, D0.y), W11); fma2(r1, pack2(D0.z, D0.w), W11);
            fma2(r2, pack2(D1.x, D1.y), W11); fma2(r3, pack2(D1.z, D1.w), W11);
            float s0, s1, s2, s3, s4, s5, s6, s7;
            unpack2(r0, s0, s1); unpack2(r1, s2, s3);
            unpack2(r2, s4, s5); unpack2(r3, s6, s7);
            u32 sa = swz((u32)(lp * 128 + l8 * 16));
            sts128(aHiB + sa, bfhi2(s0, s1), bfhi2(s2, s3), bfhi2(s4, s5), bfhi2(s6, s7));
            sts128(aLoB + sa, bflo2(s0, s1), bflo2(s2, s3), bflo2(s4, s5), bflo2(s6, s7));
        }
        __syncthreads();
        {
            int mbase = (wid & 3) * 32, nbase = (wid >> 2) * 32;
            u32 arow = (u32)((mbase + (ln & 15)) * 128 + ((ln >> 4) * 16));
            u32 brow = (u32)((nbase + ((ln >> 4) << 3) + (ln & 7)) * 128 + (((ln >> 3) & 1) * 16));
            #pragma unroll
            for (int k = 0; k < 4; k++) {
                u32 ka = (u32)(k * 32);
                u32 ah[8], al[8], bh[8], bl[8];
                ldsm4(aHiB + swz(arow + ka),        ah[0], ah[1], ah[2], ah[3]);
                ldsm4(aHiB + swz(arow + 2048 + ka), ah[4], ah[5], ah[6], ah[7]);
                ldsm4(aLoB + swz(arow + ka),        al[0], al[1], al[2], al[3]);
                ldsm4(aLoB + swz(arow + 2048 + ka), al[4], al[5], al[6], al[7]);
                ldsm4(bHiB + swz(brow + ka),        bh[0], bh[1], bh[2], bh[3]);
                ldsm4(bHiB + swz(brow + 2048 + ka), bh[4], bh[5], bh[6], bh[7]);
                ldsm4(bLoB + swz(brow + ka),        bl[0], bl[1], bl[2], bl[3]);
                ldsm4(bLoB + swz(brow + 2048 + ka), bl[4], bl[5], bl[6], bl[7]);
                #pragma unroll
                for (int mt = 0; mt < 2; mt++) {
                    #pragma unroll
                    for (int nt = 0; nt < 4; nt++) {
                        mma_bf16(acc[mt][nt][0], acc[mt][nt][1], acc[mt][nt][2], acc[mt][nt][3],
                                 ah[mt*4], ah[mt*4+1], ah[mt*4+2], ah[mt*4+3], bh[nt*2], bh[nt*2+1]);
                        mma_bf16(acc[mt][nt][0], acc[mt][nt][1], acc[mt][nt][2], acc[mt][nt][3],
                                 al[mt*4], al[mt*4+1], al[mt*4+2], al[mt*4+3], bh[nt*2], bh[nt*2+1]);
                        mma_bf16(acc[mt][nt][0], acc[mt][nt][1], acc[mt][nt][2], acc[mt][nt][3],
                                 ah[mt*4], ah[mt*4+1], ah[mt*4+2], ah[mt*4+3], bl[nt*2], bl[nt*2+1]);
                    }
                }
            }
        }
    }

    // ================= epilogue =================
    {
        int mbase = (wid & 3) * 32, nbase = (wid >> 2) * 32;
        #pragma unroll
        for (int mt = 0; mt < 2; mt++) {
            #pragma unroll
            for (int nt = 0; nt < 4; nt++) {
                int pix = p0 + mbase + mt * 16 + (ln >> 2);
                int oc  = nbase + nt * 8 + (ln & 3) * 2;
                float b0 = __ldg(bker + oc), b1 = __ldg(bker + oc + 1);
                size_t base = ((size_t)(b * 64 + oc)) * NPIX + pix;
                out[base]            = acc[mt][nt][0] + b0;
                out[base + NPIX]     = acc[mt][nt][1] + b1;
                out[base + 8]        = acc[mt][nt][2] + b0;
                out[base + NPIX + 8] = acc[mt][nt][3] + b1;
            }
        }
    }
}

// ================= launch =================
extern "C" void kernel_launch(void* const* d_in, const int* in_sizes, int n_in,
                              void* d_out, int out_size) {
    const float* x     = (const float*)d_in[0];
    const float* w_off = (const float*)d_in[1];
    const float* b_off = (const float*)d_in[2];
    const float* w_ker = (const float*)d_in[3];
    const float* b_ker = (const float*)d_in[4];
    float* out = (float*)d_out;

    cudaFuncSetAttribute(k_main, cudaFuncAttributeMaxDynamicSharedMemorySize, SMEM_MAIN);

    k_transpose<<<dim3(NPIX / 64, BB), 256>>>(x);
    k_prep<<<(9 * 4096 + 9 * 2048 + 255) / 256, 256>>>(w_ker, w_off);
    k_main<<<dim3(NPIX / 128, BB), 256, SMEM_MAIN>>>(b_off, b_ker, out);
}